// round 10
// baseline (speedup 1.0000x reference)
#include <cuda_runtime.h>
#include <math.h>

#define NB    32
#define HH    128
#define WW    128
#define CC    80
#define CHN   84
#define KTOP  100
#define CAP   8192
#define SORTN 2048

#define THR   320
#define RING  6
#define SLOTF 2720          /* 34 x * 80 ch floats per row slot */
#define ROWF4 680
#define YT    32
#define DYNSMEM (RING * SLOTF * 4)

#define FRAW  3.0f          /* compile-time window-max floor (raw space) */
#define FGATE 2.9967f       /* center gate: logit(sigma(3)-1e-4)-margin  */

__device__ unsigned g_seg[NB][6][80];     /* zero-init = bottom of ord-map */
__device__ unsigned g_count[NB];
__device__ unsigned long long g_cand[NB][CAP];

__device__ __forceinline__ unsigned su32(const void* p) {
    return (unsigned)__cvta_generic_to_shared(p);
}
__device__ __forceinline__ unsigned ordmap(float x) {
    unsigned u = __float_as_uint(x);
    return (u & 0x80000000u) ? ~u : (u | 0x80000000u);
}
__device__ __forceinline__ float ordunmap(unsigned u) {
    return __uint_as_float((u & 0x80000000u) ? (u ^ 0x80000000u) : ~u);
}
__device__ __forceinline__ int segof(int x) {
    return x == 0 ? 0 : (x < 63 ? 1 : (x == 63 ? 2 : (x == 64 ? 3 : (x < 127 ? 4 : 5))));
}

// ===== Kernel 1 (single pass): peak detect @ fixed floor + segment maxima ====
__global__ void __launch_bounds__(THR, 2) fused_kernel(const float* __restrict__ det) {
    extern __shared__ __align__(16) float ring[];
    __shared__ unsigned smax[6][80];

    const int b   = blockIdx.z;
    const int x0  = blockIdx.x * 32;
    const int y0  = blockIdx.y * YT;
    const int tid = threadIdx.x;
    const int c4  = (tid % 20) * 4;
    const int xg  = tid / 20;                   // 0..15, 2 output x each

    for (int i = tid; i < 480; i += THR) ((unsigned*)smax)[i] = 0u;

    auto issue_row = [&](int ry) {
        int gy = min(HH - 1, max(0, y0 - 1 + ry));
        const float* rp = det + (size_t)(b * HH + gy) * WW * CHN;
        float* slot = ring + (ry % RING) * SLOTF;
        #pragma unroll
        for (int u = 0; u < 3; u++) {
            int i = tid + u * THR;
            if (i < ROWF4) {
                int xl = i / 20, q = i - xl * 20;
                int gx = min(WW - 1, max(0, x0 - 1 + xl));
                asm volatile("cp.async.cg.shared.global [%0], [%1], 16;"
                             :: "r"(su32(slot + xl * 80 + q * 4)),
                                "l"(rp + gx * CHN + q * 4));
            }
        }
        asm volatile("cp.async.commit_group;");
    };

    issue_row(0); issue_row(1); issue_row(2); issue_row(3);

    const float NEGINF = __int_as_float(0xff800000);
    float4 cm0 = make_float4(NEGINF, NEGINF, NEGINF, NEGINF);
    float4 cm1 = cm0;

    for (int y = 0; y < YT; y++) {
        if (y + 4 <= YT + 1) issue_row(y + 4);
        else asm volatile("cp.async.commit_group;");
        asm volatile("cp.async.wait_group 2;");         // rows <= y+2 resident
        __syncthreads();

        const float* r0 = ring + ( y      % RING) * SLOTF;
        const float* r1 = ring + ((y + 1) % RING) * SLOTF;
        const float* r2 = ring + ((y + 2) % RING) * SLOTF;
        const int gy   = y0 + y;
        const int col1 = 2 * xg + 1;

        // center values (always needed: column maxima for certification)
        float4 c0 = *(const float4*)(r1 + col1 * 80 + c4);
        float4 c1 = *(const float4*)(r1 + (col1 + 1) * 80 + c4);
        cm0.x = fmaxf(cm0.x, c0.x); cm0.y = fmaxf(cm0.y, c0.y);
        cm0.z = fmaxf(cm0.z, c0.z); cm0.w = fmaxf(cm0.w, c0.w);
        cm1.x = fmaxf(cm1.x, c1.x); cm1.y = fmaxf(cm1.y, c1.y);
        cm1.z = fmaxf(cm1.z, c1.z); cm1.w = fmaxf(cm1.w, c1.w);

        float h = fmaxf(fmaxf(fmaxf(c0.x, c0.y), fmaxf(c0.z, c0.w)),
                        fmaxf(fmaxf(c1.x, c1.y), fmaxf(c1.z, c1.w)));
        if (h >= FGATE) {                               // ~1% of thread-rows
            #pragma unroll
            for (int xx = 0; xx < 2; xx++) {
                int col = col1 + xx;
                #pragma unroll
                for (int cc = 0; cc < 4; cc++) {
                    int ch = c4 + cc;
                    float ctr = r1[col * 80 + ch];
                    if (ctr < FGATE) continue;
                    float mm = ctr;
                    #pragma unroll
                    for (int dx = -1; dx <= 1; dx++) {
                        int cx = (col + dx) * 80 + ch;
                        mm = fmaxf(mm, fmaxf(r0[cx], fmaxf(r1[cx], r2[cx])));
                    }
                    float d = mm - ctr;
                    bool cand = false;
                    if (mm >= FRAW) {
                        if (d < 3.6e-4f) cand = true;     // sig-diff <= d/4 < 1e-4
                        else if (d < 0.0421f ||
                                 fmaxf(fabsf(ctr), fabsf(mm)) >= 6.0f) {
                            float s  = 1.0f / (1.0f + expf(-ctr));
                            float sm = 1.0f / (1.0f + expf(-mm));
                            cand = fabsf(s - sm) < 1e-4f;
                        }
                    }
                    if (cand) {
                        float sg = 1.0f / (1.0f + expf(-mm));
                        unsigned idx = ((unsigned)gy * WW
                                      + (unsigned)(x0 + col - 1)) * CC + (unsigned)ch;
                        unsigned pos = atomicAdd(&g_count[b], 1u);
                        if (pos < CAP)
                            g_cand[b][pos] =
                                ((unsigned long long)__float_as_uint(sg) << 21)
                              | (unsigned long long)(0x1FFFFFu - idx);
                    }
                }
            }
        }
        __syncthreads();
    }

    // fold per-thread column maxima into per-(segment, channel) maxima
    {
        int gx0 = x0 + 2 * xg, gx1 = gx0 + 1;
        int s0 = segof(gx0), s1 = segof(gx1);
        atomicMax(&smax[s0][c4 + 0], ordmap(cm0.x));
        atomicMax(&smax[s0][c4 + 1], ordmap(cm0.y));
        atomicMax(&smax[s0][c4 + 2], ordmap(cm0.z));
        atomicMax(&smax[s0][c4 + 3], ordmap(cm0.w));
        atomicMax(&smax[s1][c4 + 0], ordmap(cm1.x));
        atomicMax(&smax[s1][c4 + 1], ordmap(cm1.y));
        atomicMax(&smax[s1][c4 + 2], ordmap(cm1.z));
        atomicMax(&smax[s1][c4 + 3], ordmap(cm1.w));
    }
    __syncthreads();
    for (int i = tid; i < 480; i += THR)
        atomicMax(&((unsigned*)g_seg[b])[i], ((unsigned*)smax)[i]);
}

// ===== Kernel 2: certify floor, filter, sort, decode =========================
__global__ void __launch_bounds__(1024) topk_kernel(const float* __restrict__ det,
                                                    float* __restrict__ out) {
    const int b   = blockIdx.x;
    const int tid = threadIdx.x;
    __shared__ unsigned long long sel[SORTN];
    __shared__ unsigned s_vals[256];
    __shared__ float s_sT;
    __shared__ int s_n, s_fall;

    // --- certified T: per (half, channel), interior max == region max ⇒ peak --
    if (tid < 256) {
        unsigned val = 0u;
        if (tid < 160) {
            int h = tid / 80, ch = tid % 80;
            volatile unsigned* R = &g_seg[b][0][ch];
            unsigned R0 = R[0], R1 = R[80], R2 = R[160],
                     R3 = R[240], R4 = R[320], R5 = R[400];
            unsigned iu = h == 0 ? max(R1, R2) : max(R3, R4);
            unsigned ru = h == 0 ? max(iu, max(R0, R3)) : max(iu, max(R2, R5));
            if (iu == ru) val = iu;
        }
        s_vals[tid] = val;
    }
    if (tid == 0) s_n = 0;
    __syncthreads();
    for (unsigned k = 2; k <= 256; k <<= 1)
        for (unsigned j = k >> 1; j > 0; j >>= 1) {
            if (tid < 256) {
                unsigned i = (unsigned)tid, ixj = i ^ j;
                if (ixj > i) {
                    unsigned a = s_vals[i], q = s_vals[ixj];
                    bool desc = ((i & k) == 0);
                    if (desc ? (a < q) : (a > q)) { s_vals[i] = q; s_vals[ixj] = a; }
                }
            }
            __syncthreads();
        }
    unsigned cnt = g_count[b];
    if (tid == 0) {
        float T = (s_vals[99] == 0u) ? -1e30f : ordunmap(s_vals[99]);
        s_fall = (T < FRAW) || (cnt > CAP);
        s_sT   = 1.0f / (1.0f + expf(-T)) - 1e-4f;
    }
    __syncthreads();
    const float sT = s_sT;

    if (!s_fall) {
        // --- normal path: filter stored candidates by certified threshold ---
        if (cnt > CAP) cnt = CAP;
        for (unsigned i = (unsigned)tid; i < cnt; i += 1024) {
            unsigned long long key = g_cand[b][i];
            float sg = __uint_as_float((unsigned)(key >> 21));
            if (sg >= sT) {
                int p = atomicAdd(&s_n, 1);
                if (p < SORTN) sel[p] = key;
            }
        }
    } else {
        // --- fallback (never taken on valid floor): brute-force rescan ---
        for (int i = tid; i < HH * WW * CC; i += 1024) {
            int ch = i % CC, sp = i / CC, xs = sp % WW, ys = sp / WW;
            const float* base = det + ((size_t)b * HH) * WW * CHN;
            float ctr = base[((size_t)ys * WW + xs) * CHN + ch];
            float mm = ctr;
            for (int dy = -1; dy <= 1; dy++) {
                int yy = min(HH - 1, max(0, ys + dy));
                for (int dx = -1; dx <= 1; dx++) {
                    int xx = min(WW - 1, max(0, xs + dx));
                    mm = fmaxf(mm, base[((size_t)yy * WW + xx) * CHN + ch]);
                }
            }
            float s  = 1.0f / (1.0f + expf(-ctr));
            float sm = 1.0f / (1.0f + expf(-mm));
            if (fabsf(s - sm) < 1e-4f && sm >= sT) {
                int p = atomicAdd(&s_n, 1);
                if (p < SORTN) {
                    unsigned idx = ((unsigned)ys * WW + (unsigned)xs) * CC
                                 + (unsigned)ch;
                    sel[p] = ((unsigned long long)__float_as_uint(sm) << 21)
                           | (unsigned long long)(0x1FFFFFu - idx);
                }
            }
        }
    }
    __syncthreads();
    int n = s_n; if (n > SORTN) n = SORTN;
    unsigned n2 = 128;
    while (n2 < (unsigned)n) n2 <<= 1;
    for (unsigned i = (unsigned)tid; i < n2; i += 1024)
        if (i >= (unsigned)n) sel[i] = 0ull;
    __syncthreads();

    for (unsigned k = 2; k <= n2; k <<= 1)
        for (unsigned j = k >> 1; j > 0; j >>= 1) {
            for (unsigned i = (unsigned)tid; i < n2; i += 1024) {
                unsigned ixj = i ^ j;
                if (ixj > i) {
                    unsigned long long a = sel[i], q = sel[ixj];
                    bool desc = ((i & k) == 0);
                    if (desc ? (a < q) : (a > q)) { sel[i] = q; sel[ixj] = a; }
                }
            }
            __syncthreads();
        }

    if (tid < KTOP) {
        unsigned long long key = sel[tid];
        float score = 0.0f; unsigned idx = 0u;
        if (tid < n) {
            score = __uint_as_float((unsigned)(key >> 21));
            idx   = 0x1FFFFFu - (unsigned)(key & 0x1FFFFFull);
        }
        unsigned cl = idx % CC;
        unsigned sp = idx / CC;
        unsigned xs = sp % WW;
        unsigned ys = sp / WW;
        const float* wh = det + (((size_t)b * HH + ys) * WW + xs) * CHN + CC;
        float w0 = wh[0], w1 = wh[1], w2 = wh[2], w3 = wh[3];
        float fy = (float)ys, fx = (float)xs;
        float* o = out + ((size_t)b * KTOP + tid) * 6;
        o[0] = (fy - w0) * 0.0078125f;
        o[1] = (fx - w1) * 0.0078125f;
        o[2] = (fy + w2) * 0.0078125f;
        o[3] = (fx + w3) * 0.0078125f;
        o[4] = (float)cl;
        o[5] = score;
    }

    // reset per-batch state for next graph replay
    __syncthreads();
    if (tid < 480) ((unsigned*)g_seg[b])[tid] = 0u;
    if (tid == 0) g_count[b] = 0u;
}

extern "C" void kernel_launch(void* const* d_in, const int* in_sizes, int n_in,
                              void* d_out, int out_size) {
    const float* det = (const float*)d_in[0];
    float* out = (float*)d_out;
    (void)in_sizes; (void)n_in; (void)out_size;

    cudaFuncSetAttribute(fused_kernel,
                         cudaFuncAttributeMaxDynamicSharedMemorySize, DYNSMEM);

    fused_kernel<<<dim3(4, HH / YT, NB), THR, DYNSMEM>>>(det);
    topk_kernel<<<NB, 1024>>>(det, out);
}

// round 11
// speedup vs baseline: 1.2808x; 1.2808x over previous
#include <cuda_runtime.h>
#include <math.h>

#define NB    32
#define HH    128
#define WW    128
#define CC    80
#define CHN   84
#define KTOP  100
#define CAP   2048
#define SORTN 2048

#define THR   320
#define RING  6
#define SLOTF 2720          /* 34 x * 80 ch floats per row slot */
#define ROWF4 680
#define YT    32
#define DYNSMEM (RING * SLOTF * 4)

__device__ unsigned g_seg[NB][6][80];     /* zero-init = bottom of ord-map */
__device__ unsigned g_predone[NB];
__device__ float    g_T[NB], g_Tg[NB];
__device__ unsigned g_count[NB];
__device__ unsigned long long g_cand[NB][CAP];

__device__ __forceinline__ unsigned su32(const void* p) {
    return (unsigned)__cvta_generic_to_shared(p);
}
__device__ __forceinline__ unsigned ordmap(float x) {
    unsigned u = __float_as_uint(x);
    return (u & 0x80000000u) ? ~u : (u | 0x80000000u);
}
__device__ __forceinline__ float ordunmap(unsigned u) {
    return __uint_as_float((u & 0x80000000u) ? (u ^ 0x80000000u) : ~u);
}
__device__ __forceinline__ void upd4(float4& a, float4 v) {
    a.x = fmaxf(a.x, v.x); a.y = fmaxf(a.y, v.y);
    a.z = fmaxf(a.z, v.z); a.w = fmaxf(a.w, v.w);
}

// ===== Kernel 1: certified-peak threshold (512 blocks, half-row threads) =====
// Segments per channel: {0}, [1..62], {63}, {64}, [65..126], {127}.
// interior1=[1..63], region1=[0..64]; interior2=[64..126], region2=[63..127].
// If interior max == region max, that value is a guaranteed true peak
// (its 3x3 window lies inside the region, so no neighbor exceeds it).
// Thread layout: 8 rows/block, 2 halves/row, 20 ch-groups -> 320 threads.
// Half h covers x in [h*64, h*64+63], which is exactly segments 3h..3h+2.
__global__ void __launch_bounds__(320, 4) pre_kernel(const float* __restrict__ det) {
    __shared__ unsigned sm_max[6][80];
    __shared__ unsigned s_vals[256];
    __shared__ int s_last;

    const int t    = threadIdx.x;
    const int b    = blockIdx.y;
    const int row  = blockIdx.x * 8 + t / 40;       // 16 strips of 8 rows
    const int half = (t / 20) & 1;
    const int cg   = (t % 20) * 4;

    for (int i = t; i < 480; i += 320) ((unsigned*)sm_max)[i] = 0u;
    __syncthreads();

    const float NEGINF = __int_as_float(0xff800000);
    const float* rp = det + ((size_t)(b * HH + row) * WW + half * 64) * CHN + cg;

    float4 m0 = *(const float4*)(rp);                  // x-offset 0  -> seg 3h
    float4 m1 = make_float4(NEGINF, NEGINF, NEGINF, NEGINF);
    #pragma unroll 8
    for (int x = 1; x < 63; x++) upd4(m1, *(const float4*)(rp + x * CHN));
    float4 m2 = *(const float4*)(rp + 63 * CHN);       // x-offset 63 -> seg 3h+2

    const int sb = half * 3;
    atomicMax(&sm_max[sb + 0][cg + 0], ordmap(m0.x));
    atomicMax(&sm_max[sb + 0][cg + 1], ordmap(m0.y));
    atomicMax(&sm_max[sb + 0][cg + 2], ordmap(m0.z));
    atomicMax(&sm_max[sb + 0][cg + 3], ordmap(m0.w));
    atomicMax(&sm_max[sb + 1][cg + 0], ordmap(m1.x));
    atomicMax(&sm_max[sb + 1][cg + 1], ordmap(m1.y));
    atomicMax(&sm_max[sb + 1][cg + 2], ordmap(m1.z));
    atomicMax(&sm_max[sb + 1][cg + 3], ordmap(m1.w));
    atomicMax(&sm_max[sb + 2][cg + 0], ordmap(m2.x));
    atomicMax(&sm_max[sb + 2][cg + 1], ordmap(m2.y));
    atomicMax(&sm_max[sb + 2][cg + 2], ordmap(m2.z));
    atomicMax(&sm_max[sb + 2][cg + 3], ordmap(m2.w));
    __syncthreads();

    for (int i = t; i < 480; i += 320)
        atomicMax(&((unsigned*)g_seg[b])[i], ((unsigned*)sm_max)[i]);
    __threadfence();
    __syncthreads();
    if (t == 0) s_last = (atomicAdd(&g_predone[b], 1u) == 15u);  // 16 blocks/batch
    __syncthreads();
    if (!s_last) return;
    __threadfence();

    // ---- last block of this batch: select T = 100th certified peak value ----
    if (t < 256) {
        unsigned val = 0u;
        if (t < 160) {
            int h = t / 80, ch = t % 80;
            volatile unsigned* R = &g_seg[b][0][ch];
            unsigned R0 = R[0], R1 = R[80], R2 = R[160],
                     R3 = R[240], R4 = R[320], R5 = R[400];
            unsigned iu = h == 0 ? max(R1, R2) : max(R3, R4);
            unsigned ru = h == 0 ? max(iu, max(R0, R3)) : max(iu, max(R2, R5));
            if (iu == ru) val = iu;
        }
        s_vals[t] = val;
    }
    __syncthreads();
    for (unsigned k = 2; k <= 256; k <<= 1)
        for (unsigned j = k >> 1; j > 0; j >>= 1) {
            if (t < 256) {
                unsigned i = (unsigned)t, ixj = i ^ j;
                if (ixj > i) {
                    unsigned a = s_vals[i], q = s_vals[ixj];
                    bool desc = ((i & k) == 0);
                    if (desc ? (a < q) : (a > q)) { s_vals[i] = q; s_vals[ixj] = a; }
                }
            }
            __syncthreads();
        }
    if (t == 0) {
        unsigned Tm = s_vals[99];
        float T, Tg;
        if (Tm == 0u) { T = -1e30f; Tg = -1e30f; }
        else {
            T = ordunmap(Tm);
            float sT = 1.0f / (1.0f + expf(-T));
            float a  = sT - 1e-4f;
            Tg = (a <= 0.0f) ? -1e30f : (logf(a / (1.0f - a)) - 1e-3f);
        }
        g_T[b] = T; g_Tg[b] = Tg;
    }
    // reset for next graph replay
    for (int i = t; i < 480; i += 320) ((unsigned*)g_seg[b])[i] = 0u;
    if (t == 0) g_predone[b] = 0u;
}

// ===== Kernel 2: peak detect with precomputed gate ==========================
// Batches processed in REVERSE launch order: pre_kernel read batches 0..31
// ascending, so high batches are freshest in L2 when this kernel starts.
__global__ void __launch_bounds__(THR, 2) peak_kernel(const float* __restrict__ det) {
    extern __shared__ __align__(16) float ring[];
    const int b   = (NB - 1) - blockIdx.z;      // reverse for L2 reuse
    const int x0  = blockIdx.x * 32;
    const int y0  = blockIdx.y * YT;
    const int tid = threadIdx.x;
    const int c4  = (tid % 20) * 4;
    const int xg  = tid / 20;                   // 0..15, 2 output x each

    const float Tval = g_T[b];
    const float Tg   = g_Tg[b];

    auto issue_row = [&](int ry) {
        int gy = min(HH - 1, max(0, y0 - 1 + ry));
        const float* rp = det + (size_t)(b * HH + gy) * WW * CHN;
        float* slot = ring + (ry % RING) * SLOTF;
        #pragma unroll
        for (int u = 0; u < 3; u++) {
            int i = tid + u * THR;
            if (i < ROWF4) {
                int xl = i / 20, q = i - xl * 20;
                int gx = min(WW - 1, max(0, x0 - 1 + xl));
                asm volatile("cp.async.cg.shared.global [%0], [%1], 16;"
                             :: "r"(su32(slot + xl * 80 + q * 4)),
                                "l"(rp + gx * CHN + q * 4));
            }
        }
        asm volatile("cp.async.commit_group;");
    };

    issue_row(0); issue_row(1); issue_row(2); issue_row(3);

    for (int y = 0; y < YT; y++) {
        if (y + 4 <= YT + 1) issue_row(y + 4);
        else asm volatile("cp.async.commit_group;");
        asm volatile("cp.async.wait_group 2;");         // rows <= y+2 resident
        __syncthreads();

        const float* r0 = ring + ( y      % RING) * SLOTF;
        const float* r1 = ring + ((y + 1) % RING) * SLOTF;
        const float* r2 = ring + ((y + 2) % RING) * SLOTF;
        const int gy   = y0 + y;
        const int col1 = 2 * xg + 1;

        // FAST PATH: only the two center float4s
        float4 c0 = *(const float4*)(r1 + col1 * 80 + c4);
        float4 c1 = *(const float4*)(r1 + (col1 + 1) * 80 + c4);
        float h = fmaxf(fmaxf(fmaxf(c0.x, c0.y), fmaxf(c0.z, c0.w)),
                        fmaxf(fmaxf(c1.x, c1.y), fmaxf(c1.z, c1.w)));
        if (h >= Tg) {                                   // rare (~1.4e-3/thread-row)
            #pragma unroll
            for (int xx = 0; xx < 2; xx++) {
                int col = col1 + xx;
                #pragma unroll
                for (int cc = 0; cc < 4; cc++) {
                    int ch = c4 + cc;
                    float ctr = r1[col * 80 + ch];
                    if (ctr < Tg) continue;
                    float mm = ctr;
                    #pragma unroll
                    for (int dx = -1; dx <= 1; dx++) {
                        int cx = (col + dx) * 80 + ch;
                        mm = fmaxf(mm, fmaxf(r0[cx], fmaxf(r1[cx], r2[cx])));
                    }
                    float d = mm - ctr;
                    bool cand = false;
                    if (mm >= Tval) {
                        if (d < 3.6e-4f) cand = true;     // sig-diff <= d/4 < 1e-4
                        else if (d < 0.0421f ||
                                 fmaxf(fabsf(ctr), fabsf(mm)) >= 6.0f) {
                            float s  = 1.0f / (1.0f + expf(-ctr));
                            float sm = 1.0f / (1.0f + expf(-mm));
                            cand = fabsf(s - sm) < 1e-4f;
                        }
                    }
                    if (cand) {
                        float sg = 1.0f / (1.0f + expf(-mm));
                        unsigned idx = ((unsigned)gy * WW
                                      + (unsigned)(x0 + col - 1)) * CC + (unsigned)ch;
                        unsigned pos = atomicAdd(&g_count[b], 1u);
                        if (pos < CAP)
                            g_cand[b][pos] =
                                ((unsigned long long)__float_as_uint(sg) << 21)
                              | (unsigned long long)(0x1FFFFFu - idx);
                    }
                }
            }
        }
        __syncthreads();
    }
}

// ===== Kernel 3: per-batch sort + decode (dynamic bitonic size) =============
__global__ void __launch_bounds__(1024) topk_kernel(const float* __restrict__ det,
                                                    float* __restrict__ out) {
    const int b   = blockIdx.x;
    const int tid = threadIdx.x;
    __shared__ unsigned long long sel[SORTN];

    unsigned cnt = g_count[b]; if (cnt > CAP) cnt = CAP;
    unsigned n2 = 256;                       // smallest pow2 >= cnt (min 256)
    while (n2 < cnt) n2 <<= 1;

    for (unsigned i = (unsigned)tid; i < n2; i += 1024)
        sel[i] = (i < cnt) ? g_cand[b][i] : 0ull;
    __syncthreads();

    for (unsigned k = 2; k <= n2; k <<= 1)
        for (unsigned j = k >> 1; j > 0; j >>= 1) {
            for (unsigned i = (unsigned)tid; i < n2; i += 1024) {
                unsigned ixj = i ^ j;
                if (ixj > i) {
                    unsigned long long a = sel[i], q = sel[ixj];
                    bool desc = ((i & k) == 0);
                    if (desc ? (a < q) : (a > q)) { sel[i] = q; sel[ixj] = a; }
                }
            }
            __syncthreads();
        }

    if (tid < KTOP) {
        unsigned long long key = sel[tid];
        float score = 0.0f; unsigned idx = 0u;
        if ((unsigned)tid < cnt) {
            score = __uint_as_float((unsigned)(key >> 21));
            idx   = 0x1FFFFFu - (unsigned)(key & 0x1FFFFFull);
        }
        unsigned cl = idx % CC;
        unsigned sp = idx / CC;
        unsigned xs = sp % WW;
        unsigned ys = sp / WW;
        const float* wh = det + (((size_t)b * HH + ys) * WW + xs) * CHN + CC;
        float w0 = wh[0], w1 = wh[1], w2 = wh[2], w3 = wh[3];
        float fy = (float)ys, fx = (float)xs;
        float* o = out + ((size_t)b * KTOP + tid) * 6;
        o[0] = (fy - w0) * 0.0078125f;
        o[1] = (fx - w1) * 0.0078125f;
        o[2] = (fy + w2) * 0.0078125f;
        o[3] = (fx + w3) * 0.0078125f;
        o[4] = (float)cl;
        o[5] = score;
    }
    if (tid == 0) g_count[b] = 0u;          // reset for next graph replay
}

extern "C" void kernel_launch(void* const* d_in, const int* in_sizes, int n_in,
                              void* d_out, int out_size) {
    const float* det = (const float*)d_in[0];
    float* out = (float*)d_out;
    (void)in_sizes; (void)n_in; (void)out_size;

    cudaFuncSetAttribute(peak_kernel,
                         cudaFuncAttributeMaxDynamicSharedMemorySize, DYNSMEM);

    pre_kernel<<<dim3(16, NB), 320>>>(det);
    peak_kernel<<<dim3(4, HH / YT, NB), THR, DYNSMEM>>>(det);
    topk_kernel<<<NB, 1024>>>(det, out);
}

// round 13
// speedup vs baseline: 1.4896x; 1.1630x over previous
#include <cuda_runtime.h>
#include <math.h>

#define NB    32
#define HH    128
#define WW    128
#define CC    80
#define CHN   84
#define KTOP  100
#define SORTN 2048
#define QCAP  6144
#define NITEM (HH * 16 * 20)       /* 40960 scratch items per batch */

__device__ unsigned g_seg[NB][6][80];          /* zero-init = ord-map bottom */
__device__ float    g_scr[NB][HH][16][20];     /* max over 8x x 4ch cells   */

__device__ __forceinline__ unsigned ordmap(float x) {
    unsigned u = __float_as_uint(x);
    return (u & 0x80000000u) ? ~u : (u | 0x80000000u);
}
__device__ __forceinline__ float ordunmap(unsigned u) {
    return __uint_as_float((u & 0x80000000u) ? (u ^ 0x80000000u) : ~u);
}
__device__ __forceinline__ void upd4(float4& a, float4 v) {
    a.x = fmaxf(a.x, v.x); a.y = fmaxf(a.y, v.y);
    a.z = fmaxf(a.z, v.z); a.w = fmaxf(a.w, v.w);
}

// ===== Kernel 1: segment maxima (certification) + coarse max map ============
// Thread = (row, half, 4ch-group). Per half: seg m0={x0}, m1=[1..62], m2={x63}.
// Also writes per-(8x,4ch) group max to g_scr.
__global__ void __launch_bounds__(320, 3) pre_kernel(const float* __restrict__ det) {
    __shared__ unsigned sm_max[6][80];

    const int t    = threadIdx.x;
    const int b    = blockIdx.y;
    const int row  = blockIdx.x * 8 + t / 40;       // 16 strips of 8 rows
    const int half = (t / 20) & 1;
    const int cgi  = t % 20;
    const int cg   = cgi * 4;

    for (int i = t; i < 480; i += 320) ((unsigned*)sm_max)[i] = 0u;
    __syncthreads();

    const float NEGINF = __int_as_float(0xff800000);
    const float* rp = det + ((size_t)(b * HH + row) * WW + half * 64) * CHN + cg;

    float4 m0, m2;
    float4 m1 = make_float4(NEGINF, NEGINF, NEGINF, NEGINF);
    #pragma unroll
    for (int g = 0; g < 8; g++) {
        float4 a = make_float4(NEGINF, NEGINF, NEGINF, NEGINF);
        #pragma unroll
        for (int xx = 0; xx < 8; xx++) {
            float4 v = *(const float4*)(rp + (g * 8 + xx) * CHN);
            upd4(a, v);
            if (g == 0 && xx == 0)      m0 = v;
            else if (g == 7 && xx == 7) m2 = v;
            else                        upd4(m1, v);
        }
        g_scr[b][row][half * 8 + g][cgi] =
            fmaxf(fmaxf(a.x, a.y), fmaxf(a.z, a.w));
    }

    const int sb = half * 3;
    atomicMax(&sm_max[sb + 0][cg + 0], ordmap(m0.x));
    atomicMax(&sm_max[sb + 0][cg + 1], ordmap(m0.y));
    atomicMax(&sm_max[sb + 0][cg + 2], ordmap(m0.z));
    atomicMax(&sm_max[sb + 0][cg + 3], ordmap(m0.w));
    atomicMax(&sm_max[sb + 1][cg + 0], ordmap(m1.x));
    atomicMax(&sm_max[sb + 1][cg + 1], ordmap(m1.y));
    atomicMax(&sm_max[sb + 1][cg + 2], ordmap(m1.z));
    atomicMax(&sm_max[sb + 1][cg + 3], ordmap(m1.w));
    atomicMax(&sm_max[sb + 2][cg + 0], ordmap(m2.x));
    atomicMax(&sm_max[sb + 2][cg + 1], ordmap(m2.y));
    atomicMax(&sm_max[sb + 2][cg + 2], ordmap(m2.z));
    atomicMax(&sm_max[sb + 2][cg + 3], ordmap(m2.w));
    __syncthreads();

    for (int i = t; i < 480; i += 320)
        atomicMax(&((unsigned*)g_seg[b])[i], ((unsigned*)sm_max)[i]);
}

// ===== Kernel 2: certify T, scan max map, gather windows, sort, decode ======
__global__ void __launch_bounds__(1024) topk_kernel(const float* __restrict__ det,
                                                    float* __restrict__ out) {
    const int b   = blockIdx.x;
    const int tid = threadIdx.x;
    __shared__ unsigned long long sel[SORTN];     // 16KB
    __shared__ unsigned fq[QCAP];                 // 24KB fire queue
    __shared__ unsigned s_vals[256];
    __shared__ float s_T, s_Tg;
    __shared__ int s_n, s_nf;

    // --- certified T: per (half, channel), interior max == region max -> peak
    if (tid < 256) {
        unsigned val = 0u;
        if (tid < 160) {
            int h = tid / 80, ch = tid % 80;
            volatile unsigned* R = &g_seg[b][0][ch];
            unsigned R0 = R[0], R1 = R[80], R2 = R[160],
                     R3 = R[240], R4 = R[320], R5 = R[400];
            unsigned iu = h == 0 ? max(R1, R2) : max(R3, R4);
            unsigned ru = h == 0 ? max(iu, max(R0, R3)) : max(iu, max(R2, R5));
            if (iu == ru) val = iu;
        }
        s_vals[tid] = val;
    }
    if (tid == 0) { s_n = 0; s_nf = 0; }
    __syncthreads();
    for (unsigned k = 2; k <= 256; k <<= 1)
        for (unsigned j = k >> 1; j > 0; j >>= 1) {
            if (tid < 256) {
                unsigned i = (unsigned)tid, ixj = i ^ j;
                if (ixj > i) {
                    unsigned a = s_vals[i], q = s_vals[ixj];
                    bool desc = ((i & k) == 0);
                    if (desc ? (a < q) : (a > q)) { s_vals[i] = q; s_vals[ixj] = a; }
                }
            }
            __syncthreads();
        }
    if (tid == 0) {
        float T = (s_vals[99] == 0u) ? -1e30f : ordunmap(s_vals[99]);
        s_T = T;
        float sT = 1.0f / (1.0f + expf(-T));
        float a  = sT - 1e-4f;
        s_Tg = (a <= 0.0f) ? -1e30f : (logf(a / (1.0f - a)) - 1e-3f);
    }
    __syncthreads();
    const float Tval = s_T, Tg = s_Tg;

    // --- stage 1: scan coarse max map, queue fired items ---------------------
    const float* scr = &g_scr[b][0][0][0];
    for (int i = tid; i < NITEM; i += 1024) {
        if (scr[i] >= Tg) {
            int p = atomicAdd(&s_nf, 1);
            if (p < QCAP) fq[p] = (unsigned)i;
        }
    }
    __syncthreads();
    const int nf = s_nf;
    const bool fallback = (nf > QCAP);            // degenerate inputs only
    const int total = fallback ? NITEM : nf;
    const int lane = tid & 31, wid = tid >> 5;
    const float* base = det + (size_t)b * HH * WW * CHN;

    // --- stage 2: one warp per fired item, one lane per cell (8x x 4ch) ------
    for (int f = wid; f < total; f += 32) {
        unsigned item = fallback ? (unsigned)f : fq[f];
        int cgi = (int)(item % 20u);
        int rx  = (int)(item / 20u);
        int xg  = rx % 16, r = rx / 16;
        int x   = xg * 8 + (lane >> 2);
        int ch  = cgi * 4 + (lane & 3);

        float ctr = base[((size_t)r * WW + x) * CHN + ch];
        float mm = ctr;
        bool cand = false;
        if (ctr >= Tg) {
            #pragma unroll
            for (int dy = -1; dy <= 1; dy++) {
                int ry = min(HH - 1, max(0, r + dy));
                #pragma unroll
                for (int dx = -1; dx <= 1; dx++) {
                    int rxx = min(WW - 1, max(0, x + dx));
                    mm = fmaxf(mm, base[((size_t)ry * WW + rxx) * CHN + ch]);
                }
            }
            float d = mm - ctr;
            if (mm >= Tval) {
                if (d < 3.6e-4f) cand = true;        // sig-diff <= d/4 < 1e-4
                else if (d < 0.0421f ||
                         fmaxf(fabsf(ctr), fabsf(mm)) >= 6.0f) {
                    float s  = 1.0f / (1.0f + expf(-ctr));
                    float sm = 1.0f / (1.0f + expf(-mm));
                    cand = fabsf(s - sm) < 1e-4f;
                }
            }
        }
        unsigned msk = __ballot_sync(0xFFFFFFFFu, cand);
        if (msk) {
            int leader = __ffs(msk) - 1;
            unsigned bp;
            if (lane == leader) bp = (unsigned)atomicAdd(&s_n, __popc(msk));
            bp = __shfl_sync(0xFFFFFFFFu, bp, leader);
            if (cand) {
                float sg = 1.0f / (1.0f + expf(-mm));
                unsigned idx = ((unsigned)r * WW + (unsigned)x) * CC + (unsigned)ch;
                unsigned pos = bp + __popc(msk & ((1u << lane) - 1u));
                if (pos < SORTN)
                    sel[pos] = ((unsigned long long)__float_as_uint(sg) << 21)
                             | (unsigned long long)(0x1FFFFFu - idx);
            }
        }
    }
    __syncthreads();

    // --- sort (dynamic size) + decode ---------------------------------------
    int n = s_n; if (n > SORTN) n = SORTN;
    unsigned n2 = 256;
    while (n2 < (unsigned)n) n2 <<= 1;
    for (unsigned i = (unsigned)tid; i < n2; i += 1024)
        if (i >= (unsigned)n) sel[i] = 0ull;
    __syncthreads();

    for (unsigned k = 2; k <= n2; k <<= 1)
        for (unsigned j = k >> 1; j > 0; j >>= 1) {
            for (unsigned i = (unsigned)tid; i < n2; i += 1024) {
                unsigned ixj = i ^ j;
                if (ixj > i) {
                    unsigned long long a = sel[i], q = sel[ixj];
                    bool desc = ((i & k) == 0);
                    if (desc ? (a < q) : (a > q)) { sel[i] = q; sel[ixj] = a; }
                }
            }
            __syncthreads();
        }

    if (tid < KTOP) {
        unsigned long long key = sel[tid];
        float score = 0.0f; unsigned idx = 0u;
        if (tid < n) {
            score = __uint_as_float((unsigned)(key >> 21));
            idx   = 0x1FFFFFu - (unsigned)(key & 0x1FFFFFull);
        }
        unsigned cl = idx % CC;
        unsigned sp = idx / CC;
        unsigned xs = sp % WW;
        unsigned ys = sp / WW;
        const float* wh = det + (((size_t)b * HH + ys) * WW + xs) * CHN + CC;
        float w0 = wh[0], w1 = wh[1], w2 = wh[2], w3 = wh[3];
        float fy = (float)ys, fx = (float)xs;
        float* o = out + ((size_t)b * KTOP + tid) * 6;
        o[0] = (fy - w0) * 0.0078125f;
        o[1] = (fx - w1) * 0.0078125f;
        o[2] = (fy + w2) * 0.0078125f;
        o[3] = (fx + w3) * 0.0078125f;
        o[4] = (float)cl;
        o[5] = score;
    }

    // reset g_seg for next graph replay (g_scr is fully overwritten each run)
    __syncthreads();
    if (tid < 480) ((unsigned*)g_seg[b])[tid] = 0u;
}

extern "C" void kernel_launch(void* const* d_in, const int* in_sizes, int n_in,
                              void* d_out, int out_size) {
    const float* det = (const float*)d_in[0];
    float* out = (float*)d_out;
    (void)in_sizes; (void)n_in; (void)out_size;

    pre_kernel<<<dim3(16, NB), 320>>>(det);
    topk_kernel<<<NB, 1024>>>(det, out);
}